// round 16
// baseline (speedup 1.0000x reference)
#include <cuda_runtime.h>
#include <cuda_fp16.h>
#include <cstdint>
#include <cstddef>

// ---------------- scratch (static device globals; no runtime alloc) ----------
__device__ __align__(16) float g_e1[65536];            // [(b*8+h)*1024 + n]
__device__ __align__(16) float g_e2[65536];
__device__ __align__(16) float g_E2f[65536 * 2];       // per-j factor pair (Bp,Bm)
__device__ __align__(16) float g_wa[16 * 256];         // [h*2+p][i] = W[h]·a half
__device__ __align__(16) unsigned g_M1u[64];           // per-bh max e1 (encoded)
__device__ __align__(16) unsigned g_M2u[64];           // per-bh max e2 (encoded)
__device__ __align__(16) unsigned g_adjbits[8 * 1024 * 32];          // 1 MB
// fp16 single-precision GEMM inputs, k-pair interleaved within 16-groups
__device__ __align__(16) __half g_Xh[8192 * 256];      // [m][k]
__device__ __align__(16) __half g_WTh[256 * 256];      // [h*32+d][k]
// WhT for attention GEMM: fp16, [bh][d][n], n-pair interleaved in 16-groups
__device__ __align__(16) __half g_WhT_hi[64 * 32 * 1024];

// ---------------- small PTX helpers ------------------------------------------
__device__ __forceinline__ uint32_t s2u(const void* p) {
    return (uint32_t)__cvta_generic_to_shared(p);
}
__device__ __forceinline__ void cp16(uint32_t dst, const void* src) {
    asm volatile("cp.async.cg.shared.global [%0], [%1], 16;" :: "r"(dst), "l"(src));
}
__device__ __forceinline__ void cp_commit() { asm volatile("cp.async.commit_group;"); }
template <int N> __device__ __forceinline__ void cp_wait() {
    asm volatile("cp.async.wait_group %0;" :: "n"(N));
}
// pack two fp32 -> f16x2, low half = a
__device__ __forceinline__ uint32_t cvt2h(float a, float b) {
    uint32_t r; asm("cvt.rn.f16x2.f32 %0, %1, %2;" : "=r"(r) : "f"(b), "f"(a)); return r;
}
__device__ __forceinline__ uint2 lds64(uint32_t a) {
    uint2 v;
    asm volatile("ld.shared.v2.b32 {%0,%1}, [%2];" : "=r"(v.x), "=r"(v.y) : "r"(a));
    return v;
}
// fp16 D(16x8,f32) += A(16x16,f16,row) * B(16x8,f16,col)
__device__ __forceinline__ void mma16816h(float* d,
                                          uint32_t a0, uint32_t a1, uint32_t a2, uint32_t a3,
                                          uint32_t b0, uint32_t b1) {
    asm volatile(
        "mma.sync.aligned.m16n8k16.row.col.f32.f16.f16.f32 "
        "{%0,%1,%2,%3}, {%4,%5,%6,%7}, {%8,%9}, {%0,%1,%2,%3};"
        : "+f"(d[0]), "+f"(d[1]), "+f"(d[2]), "+f"(d[3])
        : "r"(a0), "r"(a1), "r"(a2), "r"(a3), "r"(b0), "r"(b1));
}
// monotone float<->uint encoding for atomicMax over signed floats
__device__ __forceinline__ unsigned encf(float f) {
    unsigned u = __float_as_uint(f);
    return (u & 0x80000000u) ? ~u : (u | 0x80000000u);
}
__device__ __forceinline__ float decf(unsigned k) {
    unsigned u = (k & 0x80000000u) ? (k ^ 0x80000000u) : ~k;
    return __uint_as_float(u);
}

__device__ __constant__ int c_perm[8] = {0, 8, 2, 10, 4, 12, 6, 14};

// ---------------- Kernel P1: X fp32 -> fp16 (k-pair interleaved) -------------
__global__ __launch_bounds__(256) void split_x_k(const float* __restrict__ X) {
    const int g = blockIdx.x * 256 + threadIdx.x;      // 131072 16-float groups
    float v[16];
    const float4* s4 = reinterpret_cast<const float4*>(X + (size_t)g * 16);
#pragma unroll
    for (int q = 0; q < 4; q++) {
        float4 f = s4[q];
        v[q * 4 + 0] = f.x; v[q * 4 + 1] = f.y;
        v[q * 4 + 2] = f.z; v[q * 4 + 3] = f.w;
    }
    uint32_t H[8];
#pragma unroll
    for (int m = 0; m < 8; m++)
        H[m] = cvt2h(v[c_perm[m]], v[c_perm[m] + 1]);
    uint4* dh = reinterpret_cast<uint4*>(g_Xh + (size_t)g * 16);
    dh[0] = make_uint4(H[0], H[1], H[2], H[3]);
    dh[1] = make_uint4(H[4], H[5], H[6], H[7]);
}

// ---------------- Kernel P2: W -> fp16 transposed (interleaved) --------------
__global__ __launch_bounds__(256) void split_w_k(const float* __restrict__ W) {
    const int task = blockIdx.x * 256 + threadIdx.x;   // 4096 tasks
    const int h   = task >> 9;
    const int d   = (task >> 4) & 31;
    const int grp = task & 15;
    const float* wp = W + (size_t)h * 8192 + (size_t)grp * 16 * 32 + d;
    float v[16];
#pragma unroll
    for (int k = 0; k < 16; k++) v[k] = wp[k * 32];
    uint32_t H[8];
#pragma unroll
    for (int m = 0; m < 8; m++)
        H[m] = cvt2h(v[c_perm[m]], v[c_perm[m] + 1]);
    const size_t off = (size_t)(h * 32 + d) * 256 + grp * 16;
    uint4* dh = reinterpret_cast<uint4*>(g_WTh + off);
    dh[0] = make_uint4(H[0], H[1], H[2], H[3]);
    dh[1] = make_uint4(H[4], H[5], H[6], H[7]);
}

// ---------------- Kernel P3: wa[h*2+p][i] = sum_j W[h][i][j]*a[h][p*32+j] ----
__global__ __launch_bounds__(256) void prep_wa_k(const float* __restrict__ W,
                                                 const float* __restrict__ av) {
    const int o = blockIdx.x;          // 0..15
    const int h = o >> 1, p = o & 1;
    const int t = threadIdx.x;         // i = t
    if (blockIdx.x == 0 && t < 64) { g_M1u[t] = 0u; g_M2u[t] = 0u; }
    __shared__ float sa32[32];
    if (t < 8)
        reinterpret_cast<float4*>(sa32)[t] =
            reinterpret_cast<const float4*>(av + h * 64 + p * 32)[t];
    __syncthreads();
    const float4* wp = reinterpret_cast<const float4*>(W + (size_t)h * 8192 + t * 32);
    float s = 0.f;
#pragma unroll
    for (int j4 = 0; j4 < 8; j4++) {
        float4 w = wp[j4];
        s += w.x * sa32[j4 * 4 + 0] + w.y * sa32[j4 * 4 + 1]
           + w.z * sa32[j4 * 4 + 2] + w.w * sa32[j4 * 4 + 3];
    }
    g_wa[o * 256 + t] = s;
}

// ---------------- Kernel A2: bitpack adjacency -------------------------------
__global__ __launch_bounds__(256) void bitpack_k(const int* __restrict__ adj) {
    const int w = blockIdx.x * 256 + threadIdx.x;
    const int4* p = reinterpret_cast<const int4*>(adj) + (size_t)w * 8;
    unsigned bits = 0;
#pragma unroll
    for (int k = 0; k < 8; k++) {
        int4 v = p[k];
        bits |= (unsigned)(v.x != 0) << (k * 4 + 0);
        bits |= (unsigned)(v.y != 0) << (k * 4 + 1);
        bits |= (unsigned)(v.z != 0) << (k * 4 + 2);
        bits |= (unsigned)(v.w != 0) << (k * 4 + 3);
    }
    g_adjbits[w] = bits;
}

// ---------------- Kernel B: exact fp32 e1/e2 from X (rank-1 refactor) --------
// e[b,h,n] = X[b,n,:]·wa[h]; grid 256 blocks, thread = (m, h).
__global__ __launch_bounds__(256) void calc_e_k(const float* __restrict__ X) {
    __shared__ float4 swaS[64][16];    // [k4][o]
    __shared__ float  sm1[8][8], sm2[8][8];
    const int t = threadIdx.x;
    for (int idx = t; idx < 1024; idx += 256) {
        int k4 = idx >> 4, o = idx & 15;
        swaS[k4][o] = *reinterpret_cast<const float4*>(g_wa + o * 256 + k4 * 4);
    }
    __syncthreads();

    const int idx = blockIdx.x * 256 + t;
    const int m = idx >> 3;            // global row (b*1024+n)
    const int h = idx & 7;
    const int bb = blockIdx.x >> 5;    // batch (32 rows per block, same b)
    const float4* xp = reinterpret_cast<const float4*>(X + (size_t)m * 256);
    float e1 = 0.f, e2 = 0.f;
#pragma unroll 8
    for (int k4 = 0; k4 < 64; k4++) {
        float4 x  = xp[k4];
        float4 w1 = swaS[k4][2 * h];
        float4 w2 = swaS[k4][2 * h + 1];
        e1 += x.x * w1.x + x.y * w1.y + x.z * w1.z + x.w * w1.w;
        e2 += x.x * w2.x + x.y * w2.y + x.z * w2.z + x.w * w2.w;
    }
    const int n = m & 1023;
    g_e1[(bb * 8 + h) * 1024 + n] = e1;
    g_e2[(bb * 8 + h) * 1024 + n] = e2;

    float m1 = e1, m2 = e2;
    m1 = fmaxf(m1, __shfl_xor_sync(0xffffffffu, m1, 8));
    m1 = fmaxf(m1, __shfl_xor_sync(0xffffffffu, m1, 16));
    m2 = fmaxf(m2, __shfl_xor_sync(0xffffffffu, m2, 8));
    m2 = fmaxf(m2, __shfl_xor_sync(0xffffffffu, m2, 16));
    const int lane = t & 31, wid = t >> 5;
    if (lane < 8) { sm1[wid][lane] = m1; sm2[wid][lane] = m2; }
    __syncthreads();
    if (t < 8) {
        float a1 = sm1[0][t], a2 = sm2[0][t];
#pragma unroll
        for (int wi = 1; wi < 8; wi++) {
            a1 = fmaxf(a1, sm1[wi][t]);
            a2 = fmaxf(a2, sm2[wi][t]);
        }
        atomicMax(&g_M1u[bb * 8 + t], encf(a1));
        atomicMax(&g_M2u[bb * 8 + t], encf(a2));
    }
}

// ---------------- Kernel G: fp16 single-product Wh GEMM + WhT epilogue -------
// Grid (64 m-tiles of 128, 4 c-tiles of 64) = 256 blocks, occ 2 -> single wave.
// Warp: wm (4) x wc (2); dual m-tiles (m, m+64) share A-slot reads and B frags.
#define G2B_OFF    40960                   // A ring 4 x 10240 first
#define G2B_STRIDE 544
#define G2SM_TOTAL (G2B_OFF + 64 * G2B_STRIDE)   // 75776

__global__ __launch_bounds__(256, 2) void gemm_mma_k() {
    extern __shared__ __align__(16) char dsm[];
    const int t    = threadIdx.x;
    const int lane = t & 31;
    const int w    = t >> 5;
    const int bm   = blockIdx.x;           // 64 tiles of 128 m-rows
    const int bn   = blockIdx.y;           // 4 tiles of 64 cols
    const int m0   = bm * 128;
    const int wm   = w >> 1;
    const int wc   = w & 1;
    const int r0   = lane >> 2;
    const int c0   = (lane & 3) * 2;

    // one-time B staging: 64 rows x 512B
    {
        const int brow = t >> 2, bseg = t & 3;
        const uint32_t bdst = s2u(dsm) + G2B_OFF + brow * G2B_STRIDE;
        const __half* bsrc = g_WTh + (size_t)(bn * 64 + brow) * 256;
#pragma unroll
        for (int q = 0; q < 8; q++) {
            const int seg = bseg + q * 4;
            cp16(bdst + seg * 16, bsrc + seg * 8);
        }
    }
    cp_commit();

    // A ring: slot = 128 rows x 80B (64B data + pad)
    const int cprow = t >> 1, chalf = t & 1;
    const __half* xsrc = g_Xh + (size_t)(m0 + cprow) * 256 + chalf * 16;
    const uint32_t adst = s2u(dsm) + cprow * 80 + chalf * 32;
#define CP_A(S)                                                               \
    {                                                                         \
        uint32_t sl = ((uint32_t)(S) & 3u) * 10240u;                          \
        cp16(adst + sl,      xsrc + (S) * 32);                                \
        cp16(adst + sl + 16, xsrc + (S) * 32 + 8);                            \
    }
    CP_A(0) cp_commit();
    CP_A(1) cp_commit();
    CP_A(2) cp_commit();

    float accA[4][4], accB[4][4];
#pragma unroll
    for (int nt = 0; nt < 4; nt++)
#pragma unroll
        for (int q = 0; q < 4; q++) { accA[nt][q] = 0.f; accB[nt][q] = 0.f; }

    const uint32_t abase = s2u(dsm) + (wm * 16 + r0) * 80 + c0 * 4;
    const uint32_t bbase = s2u(dsm) + G2B_OFF + (wc * 32 + r0) * G2B_STRIDE + c0 * 4;

    for (int s = 0; s < 8; s++) {
        cp_wait<2>();
        __syncthreads();
        if (s < 5) CP_A(s + 3)
        cp_commit();
        const uint32_t ab = abase + ((uint32_t)s & 3u) * 10240u;
#pragma unroll
        for (int ck = 0; ck < 2; ck++) {
            uint2 A0 = lds64(ab + ck * 32);                  // tile A row r0
            uint2 A1 = lds64(ab + ck * 32 + 8 * 80);         // row r0+8
            uint2 B0 = lds64(ab + ck * 32 + 64 * 80);        // tile B row r0
            uint2 B1 = lds64(ab + ck * 32 + 72 * 80);        // row r0+8
            const uint32_t bk = bbase + (s * 32 + ck * 16) * 2;
#pragma unroll
            for (int nt = 0; nt < 4; nt++) {
                uint2 Bf = lds64(bk + nt * 8 * G2B_STRIDE);
                mma16816h(accA[nt], A0.x, A1.x, A0.y, A1.y, Bf.x, Bf.y);
                mma16816h(accB[nt], B0.x, B1.x, B0.y, B1.y, Bf.x, Bf.y);
            }
        }
    }
#undef CP_A
    __syncthreads();

    // stage Wh tile as sT[c][m] fp32 in the A-ring area (64 x 132 floats)
    float* sT = reinterpret_cast<float*>(dsm);
#pragma unroll
    for (int nt = 0; nt < 4; nt++) {
        const int cl = wc * 32 + nt * 8 + c0;
        const int mA = wm * 16 + r0;
        sT[(cl + 0) * 132 + mA]       = accA[nt][0];
        sT[(cl + 1) * 132 + mA]       = accA[nt][1];
        sT[(cl + 0) * 132 + mA + 8]   = accA[nt][2];
        sT[(cl + 1) * 132 + mA + 8]   = accA[nt][3];
        sT[(cl + 0) * 132 + mA + 64]  = accB[nt][0];
        sT[(cl + 1) * 132 + mA + 64]  = accB[nt][1];
        sT[(cl + 0) * 132 + mA + 72]  = accB[nt][2];
        sT[(cl + 1) * 132 + mA + 72]  = accB[nt][3];
    }
    __syncthreads();

    // transposed fp16 WhT write (n-pair interleave per 16-group)
    {
        const int cl  = t >> 2;            // 0..63
        const int seg = t & 3;             // 32 n each
        const int b   = bm >> 3;
        const int h   = bn * 2 + (cl >> 5);
        const int d   = cl & 31;
#pragma unroll
        for (int g2 = 0; g2 < 2; g2++) {
            const int base = seg * 32 + g2 * 16;
            float v[16];
            const float4* rp = reinterpret_cast<const float4*>(&sT[cl * 132 + base]);
#pragma unroll
            for (int q = 0; q < 4; q++) {
                float4 f = rp[q];
                v[q * 4 + 0] = f.x; v[q * 4 + 1] = f.y;
                v[q * 4 + 2] = f.z; v[q * 4 + 3] = f.w;
            }
            uint32_t H[8];
#pragma unroll
            for (int m = 0; m < 8; m++)
                H[m] = cvt2h(v[c_perm[m]], v[c_perm[m] + 1]);
            const size_t off = (size_t)(b * 8 + h) * 32768 + (size_t)d * 1024
                             + (bm & 7) * 128 + base;
            uint4* dh = reinterpret_cast<uint4*>(g_WhT_hi + off);
            dh[0] = make_uint4(H[0], H[1], H[2], H[3]);
            dh[1] = make_uint4(H[4], H[5], H[6], H[7]);
        }
    }
}

// ---------------- Kernel E: per-j softmax factor pairs -----------------------
__global__ __launch_bounds__(256) void expj_k() {
    const int idx = blockIdx.x * 256 + threadIdx.x;     // 65536
    const int bh  = idx >> 10;
    const float M1 = decf(g_M1u[bh]);
    const float M2 = decf(g_M2u[bh]);
    const float s  = M1 + M2;
    const float C  = fmaxf(s, 0.2f * s);
    const float e2 = g_e2[idx];
    float2 r;
    r.x = __expf(e2 - C + M1);
    r.y = __expf(fmaf(0.2f, e2, fmaf(0.2f, M1, -C)));
    reinterpret_cast<float2*>(g_E2f)[idx] = r;
}

// ---------------- Kernel D: HMMA fused softmax + attn@Wh (unchanged) ---------
__global__ __launch_bounds__(256, 2) void gat_mma_k(const float* __restrict__ bias,
                                                    float* __restrict__ out) {
    __shared__ __align__(16) __half sB[4][32][72];      // [slot][d][j]

    const int t    = threadIdx.x;
    const int w    = t >> 5;
    const int lane = t & 31;
    const int bh   = blockIdx.y;
    const int b    = bh >> 3, h = bh & 7;
    const int i0   = blockIdx.x * 256;

    const int r0 = lane >> 2;
    const int c0 = (lane & 3) * 2;

    const int   row0 = w * 16 + r0;
    const float M1   = decf(g_M1u[bh]);
    const float M2   = decf(g_M2u[bh]);
    const float s    = M1 + M2;
    const float BPM  = (s >= 0.f) ? 1.f : __expf(0.8f * s);
    const float BMM  = (s >= 0.f) ? __expf(-0.8f * s) : 1.f;
    float Ap0, Am0, Ap1, Am1, Ap2, Am2, Ap3, Am3;
    {
        const float e1_0 = g_e1[bh * 1024 + i0 + row0];
        const float e1_1 = g_e1[bh * 1024 + i0 + row0 + 8];
        const float e1_2 = g_e1[bh * 1024 + i0 + row0 + 128];
        const float e1_3 = g_e1[bh * 1024 + i0 + row0 + 136];
        Ap0 = __expf(e1_0 - M1); Am0 = __expf(0.2f * (e1_0 - M1));
        Ap1 = __expf(e1_1 - M1); Am1 = __expf(0.2f * (e1_1 - M1));
        Ap2 = __expf(e1_2 - M1); Am2 = __expf(0.2f * (e1_2 - M1));
        Ap3 = __expf(e1_3 - M1); Am3 = __expf(0.2f * (e1_3 - M1));
        float rs0 = 1.f / fmaxf(Ap0 * BPM, Am0 * BMM);
        float rs1 = 1.f / fmaxf(Ap1 * BPM, Am1 * BMM);
        float rs2 = 1.f / fmaxf(Ap2 * BPM, Am2 * BMM);
        float rs3 = 1.f / fmaxf(Ap3 * BPM, Am3 * BMM);
        Ap0 *= rs0; Am0 *= rs0;  Ap1 *= rs1; Am1 *= rs1;
        Ap2 *= rs2; Am2 *= rs2;  Ap3 *= rs3; Am3 *= rs3;
    }

    const unsigned* __restrict__ mrow0 = g_adjbits + (size_t)(b * 1024 + i0 + row0) * 32;
    const unsigned* __restrict__ mrow1 = mrow0 + 8 * 32;
    const unsigned* __restrict__ mrow2 = mrow0 + 128 * 32;
    const unsigned* __restrict__ mrow3 = mrow0 + 136 * 32;
    const float* __restrict__ e2f = g_E2f + (size_t)bh * 2048;

    const int cpd = t >> 3, cpj = (t & 7) * 8;
    const __half* bsrc_hi = g_WhT_hi + (size_t)bh * 32768 + cpd * 1024 + cpj;
#define CP_B(C_)                                                              \
    {                                                                         \
        int sl = (C_) & 3;                                                    \
        cp16(s2u(&sB[sl][cpd][cpj]), bsrc_hi + (C_) * 64);                    \
    }
    CP_B(0) cp_commit();
    CP_B(1) cp_commit();
    CP_B(2) cp_commit();

    float accA[4][4], accB[4][4];
#pragma unroll
    for (int nt = 0; nt < 4; nt++)
#pragma unroll
        for (int q = 0; q < 4; q++) { accA[nt][q] = 0.f; accB[nt][q] = 0.f; }
    float den0 = 0.f, den1 = 0.f, den2 = 0.f, den3 = 0.f;

    for (int c = 0; c < 16; c++) {
        cp_wait<2>();
        __syncthreads();
        if (c < 13) CP_B(c + 3)
        cp_commit();
        const int sl = c & 3;

        const unsigned m0a = mrow0[2 * c], m0b = mrow0[2 * c + 1];
        const unsigned m1a = mrow1[2 * c], m1b = mrow1[2 * c + 1];
        const unsigned m2a = mrow2[2 * c], m2b = mrow2[2 * c + 1];
        const unsigned m3a = mrow3[2 * c], m3b = mrow3[2 * c + 1];

#pragma unroll
        for (int kt = 0; kt < 4; kt++) {
            const int jb = c * 64 + kt * 16;
            float4 F0 = *reinterpret_cast<const float4*>(e2f + 2 * (jb + c0));
            float4 F1 = *reinterpret_cast<const float4*>(e2f + 2 * (jb + c0 + 8));
            const int sh = ((kt & 1) * 16) + c0;
            const unsigned bits0 = ((kt >> 1) ? m0b : m0a) >> sh;
            const unsigned bits1 = ((kt >> 1) ? m1b : m1a) >> sh;
            const unsigned bits2 = ((kt >> 1) ? m2b : m2a) >> sh;
            const unsigned bits3 = ((kt >> 1) ? m3b : m3a) >> sh;

#define PP(DST, AP, AM, BP, BM, BITS, POS)                                    \
            float DST;                                                        \
            {                                                                 \
                float pe = fmaxf((AP) * (BP), (AM) * (BM));                   \
                DST = (((BITS) >> (POS)) & 1u) ? pe : 0.f;                    \
            }
            PP(p00, Ap0, Am0, F0.x, F0.y, bits0, 0)
            PP(p01, Ap0, Am0, F0.z, F0.w, bits0, 1)
            PP(p08, Ap0, Am0, F1.x, F1.y, bits0, 8)
            PP(p09, Ap0, Am0, F1.z, F1.w, bits0, 9)
            PP(p10, Ap1, Am1, F0.x, F0.y, bits1, 0)
            PP(p11, Ap1, Am1, F0.z, F0.w, bits1, 1)
            PP(p18, Ap1, Am1, F1.x, F1.y, bits1, 8)
            PP(p19, Ap1, Am1, F1.z, F1.w, bits1, 9)
            PP(q00, Ap2, Am2, F0.x, F0.y, bits2, 0)
            PP(q01, Ap2, Am2, F0.z, F0.w, bits2, 1)
            PP(q08, Ap2, Am2, F1.x, F1.y, bits2, 8)
            PP(q09, Ap2, Am2, F1.z, F1.w, bits2, 9)
            PP(q10, Ap3, Am3, F0.x, F0.y, bits3, 0)
            PP(q11, Ap3, Am3, F0.z, F0.w, bits3, 1)
            PP(q18, Ap3, Am3, F1.x, F1.y, bits3, 8)
            PP(q19, Ap3, Am3, F1.z, F1.w, bits3, 9)
#undef PP
            den0 += (p00 + p01) + (p08 + p09);
            den1 += (p10 + p11) + (p18 + p19);
            den2 += (q00 + q01) + (q08 + q09);
            den3 += (q10 + q11) + (q18 + q19);

            uint32_t a0 = cvt2h(p00, p01);
            uint32_t a1 = cvt2h(p10, p11);
            uint32_t a2 = cvt2h(p08, p09);
            uint32_t a3 = cvt2h(p18, p19);
            uint32_t b0 = cvt2h(q00, q01);
            uint32_t b1 = cvt2h(q10, q11);
            uint32_t b2 = cvt2h(q08, q09);
            uint32_t b3 = cvt2h(q18, q19);

#pragma unroll
            for (int nt = 0; nt < 4; nt++) {
                uint2 bhp = *reinterpret_cast<const uint2*>(
                    &sB[sl][nt * 8 + r0][kt * 16 + c0 * 2]);
                mma16816h(accA[nt], a0, a1, a2, a3, bhp.x, bhp.y);
                mma16816h(accB[nt], b0, b1, b2, b3, bhp.x, bhp.y);
            }
        }
    }
#undef CP_B

    den0 += __shfl_xor_sync(0xffffffffu, den0, 1);
    den0 += __shfl_xor_sync(0xffffffffu, den0, 2);
    den1 += __shfl_xor_sync(0xffffffffu, den1, 1);
    den1 += __shfl_xor_sync(0xffffffffu, den1, 2);
    den2 += __shfl_xor_sync(0xffffffffu, den2, 1);
    den2 += __shfl_xor_sync(0xffffffffu, den2, 2);
    den3 += __shfl_xor_sync(0xffffffffu, den3, 1);
    den3 += __shfl_xor_sync(0xffffffffu, den3, 2);
    const float rd0 = 1.0f / den0;
    const float rd1 = 1.0f / den1;
    const float rd2 = 1.0f / den2;
    const float rd3 = 1.0f / den3;

    float* o0 = out + ((size_t)(b * 1024 + i0 + row0)) * 256 + h * 32;
    float* o1 = o0 + 8 * 256;
    float* o2 = o0 + 128 * 256;
    float* o3 = o0 + 136 * 256;
#pragma unroll
    for (int nt = 0; nt < 4; nt++) {
        const int dcol = nt * 8 + c0;
        float2 bi = *reinterpret_cast<const float2*>(bias + h * 32 + dcol);
        float2 v0, v1, v2, v3;
        v0.x = fmaxf(accA[nt][0] * rd0 + bi.x, 0.f);
        v0.y = fmaxf(accA[nt][1] * rd0 + bi.y, 0.f);
        v1.x = fmaxf(accA[nt][2] * rd1 + bi.x, 0.f);
        v1.y = fmaxf(accA[nt][3] * rd1 + bi.y, 0.f);
        v2.x = fmaxf(accB[nt][0] * rd2 + bi.x, 0.f);
        v2.y = fmaxf(accB[nt][1] * rd2 + bi.y, 0.f);
        v3.x = fmaxf(accB[nt][2] * rd3 + bi.x, 0.f);
        v3.y = fmaxf(accB[nt][3] * rd3 + bi.y, 0.f);
        *reinterpret_cast<float2*>(o0 + dcol) = v0;
        *reinterpret_cast<float2*>(o1 + dcol) = v1;
        *reinterpret_cast<float2*>(o2 + dcol) = v2;
        *reinterpret_cast<float2*>(o3 + dcol) = v3;
    }
}

// ---------------- launcher ---------------------------------------------------
extern "C" void kernel_launch(void* const* d_in, const int* in_sizes, int n_in,
                              void* d_out, int out_size) {
    const float* nf   = (const float*)d_in[0];   // (8,1024,256)
    const int*   adj  = (const int*)d_in[1];     // (8,1024,1024)
    const float* W    = (const float*)d_in[2];   // (8,256,32)
    const float* a    = (const float*)d_in[3];   // (8,64)
    const float* bias = (const float*)d_in[4];   // (256,)
    float*       out  = (float*)d_out;           // (8,1024,256)

    cudaFuncSetAttribute(gemm_mma_k, cudaFuncAttributeMaxDynamicSharedMemorySize,
                         G2SM_TOTAL);

    split_x_k<<<512, 256>>>(nf);
    split_w_k<<<16, 256>>>(W);
    prep_wa_k<<<16, 256>>>(W, a);
    bitpack_k<<<1024, 256>>>(adj);
    calc_e_k<<<256, 256>>>(nf);
    gemm_mma_k<<<dim3(64, 4), 256, G2SM_TOTAL>>>();
    expj_k<<<256, 256>>>();
    gat_mma_k<<<dim3(4, 64), 256>>>(bias, out);
}